// round 10
// baseline (speedup 1.0000x reference)
#include <cuda_runtime.h>

// HausdorffDTLoss: B=4, C=2, H=W=256, ALPHA=2.
// Matches the reference 2-pass brute-force squared EDT to ~1 ulp per term:
//  - row pass stores packed u16 nearest-opposite-bit distances (fg low16,
//    bg high16; the half not matching the pixel's own bit is exactly 0;
//    sentinel d=1024 when the row has no opposite bit, 1024^2 = 2^20).
//  - column pass: exact integer min of d*d + r^2 (finite < 2^18; sentinel
//    sums >= 2^20 only win when every row is sentinel -> reference's 1e9).
//    Branchless window r<=4 is exact when best <= 25; rare lanes do an exact
//    global column scan. The reference's field = sqrt(D) then field^2 is
//    replaced by D directly (<= 1 ulp difference, tolerance is 1e-3).

#define HH 256
#define WW 256
#define BB 4
#define SENT 1024u
#define SENTP 0x04000400u

__device__ uint2 g_pack[BB][HH * WW];

// ---------------------------------------------------------------------------
// nearest opposite-valued bit in a 256-bit row mask
// ---------------------------------------------------------------------------
__device__ __forceinline__ int nearest_opp(const unsigned* __restrict__ w, int i,
                                           unsigned inv) {
    const int k = i >> 5, bpos = i & 31;
    unsigned m = (w[k] ^ inv) & (0xFFFFFFFFu >> (31 - bpos));
    int L = -1000000, kk = k;
    while (true) {
        if (m) { L = (kk << 5) + 31 - __clz(m); break; }
        if (--kk < 0) break;
        m = w[kk] ^ inv;
    }
    m = (w[k] ^ inv) & (0xFFFFFFFFu << bpos);
    int R = 1000000;
    kk = k;
    while (true) {
        if (m) { R = (kk << 5) + __ffs(m) - 1; break; }
        if (++kk > 7) break;
        m = w[kk] ^ inv;
    }
    return min(i - L, R - i);
}

// ---------------------------------------------------------------------------
// K1: row pass, 2 rows per block. grid=(128, 4), block=256. Also zeroes out.
// ---------------------------------------------------------------------------
__global__ __launch_bounds__(256) void k_rowpass(const float* __restrict__ mo,
                                                 const float* __restrict__ gt,
                                                 float* __restrict__ out) {
    const int rp = blockIdx.x;  // row pair
    const int b = blockIdx.y;
    const int t = threadIdx.x;

    __shared__ unsigned P[2][8], G[2][8];
    float m0[2], m1[2], gv[2];
    bool pb[2], gb[2];

#pragma unroll
    for (int k = 0; k < 2; ++k) {  // 6 independent LDGs in flight
        int r = rp * 2 + k;
        m0[k] = mo[((b * 2 + 0) * HH + r) * WW + t];
        m1[k] = mo[((b * 2 + 1) * HH + r) * WW + t];
        gv[k] = gt[(b * HH + r) * WW + t];
    }
#pragma unroll
    for (int k = 0; k < 2; ++k) {
        pb[k] = (m1[k] > m0[k]);  // argmax ties -> channel 0
        gb[k] = (gv[k] > 0.5f);
        unsigned bp = __ballot_sync(0xFFFFFFFFu, pb[k]);
        unsigned bg = __ballot_sync(0xFFFFFFFFu, gb[k]);
        if ((t & 31) == 0) {
            P[k][t >> 5] = bp;
            G[k][t >> 5] = bg;
        }
    }
    __syncthreads();

#pragma unroll
    for (int k = 0; k < 2; ++k) {
        int r = rp * 2 + k;
        int pd = nearest_opp(P[k], t, pb[k] ? 0xFFFFFFFFu : 0u);
        int gd = nearest_opp(G[k], t, gb[k] ? 0xFFFFFFFFu : 0u);
        unsigned ps = (pd > 255) ? SENT : (unsigned)pd;
        unsigned gs = (gd > 255) ? SENT : (unsigned)gd;
        uint2 o;
        o.x = pb[k] ? ps : (ps << 16);  // fg dist low16, bg dist high16
        o.y = gb[k] ? gs : (gs << 16);
        g_pack[b][r * WW + t] = o;
    }

    if (rp == 0 && b == 0 && t == 0) out[0] = 0.0f;
}

// ---------------------------------------------------------------------------
// rare exact extension beyond the r<=4 window (global column scan)
// ---------------------------------------------------------------------------
__device__ __noinline__ unsigned extend(const uint2* __restrict__ src, int i,
                                        int col, int sh, int useY,
                                        unsigned best) {
#pragma unroll 1
    for (int r = 5; r < 256; ++r) {
        unsigned rr = (unsigned)(r * r);
        if (rr >= best) break;
        int lo = i - r, hi = i + r;
        if (lo >= 0) {
            uint2 w = __ldg(&src[lo * WW + col]);
            unsigned d = ((useY ? w.y : w.x) >> sh) & 0xFFFFu;
            best = min(best, d * d + rr);
        }
        if (hi < 256) {
            uint2 w = __ldg(&src[hi * WW + col]);
            unsigned d = ((useY ? w.y : w.x) >> sh) & 0xFFFFu;
            best = min(best, d * d + rr);
        }
    }
    return best;
}

// ---------------------------------------------------------------------------
// loss term for one pixel given its 9-row register window wv[0..8]
// (wv[4] is the pixel's own row); i/col only used by the rare extension.
// ---------------------------------------------------------------------------
#define PIXEL_TERM(WV, I, COL, SRC, ACC)                                       \
    {                                                                          \
        uint2 vv = (WV)[4];                                                    \
        bool pbit = (vv.x & 0xFFFFu) != 0u;                                    \
        bool gbit = (vv.y & 0xFFFFu) != 0u;                                    \
        int shp = pbit ? 0 : 16;                                               \
        int shg = gbit ? 0 : 16;                                               \
        unsigned bestP = 0xFFFFFFFFu, bestG = 0xFFFFFFFFu;                     \
        _Pragma("unroll") for (int j = 0; j < 9; ++j) {                        \
            unsigned rr = (unsigned)((j - 4) * (j - 4));                       \
            unsigned dp = ((WV)[j].x >> shp) & 0xFFFFu;                        \
            unsigned dg = ((WV)[j].y >> shg) & 0xFFFFu;                        \
            bestP = min(bestP, dp * dp + rr);                                  \
            bestG = min(bestG, dg * dg + rr);                                  \
        }                                                                      \
        if (bestP > 25u) bestP = extend((SRC), (I), (COL), shp, 0, bestP);     \
        if (bestG > 25u) bestG = extend((SRC), (I), (COL), shg, 1, bestG);     \
        if (pbit != gbit) {                                                    \
            float pt = (bestP >= (1u << 20))                                   \
                           ? (pbit ? 1.0e9f : 0.0f)                            \
                           : (float)bestP;                                     \
            float gtv = (bestG >= (1u << 20))                                  \
                            ? (gbit ? 1.0e9f : 0.0f)                           \
                            : (float)bestG;                                    \
            (ACC) += pt + gtv;                                                 \
        }                                                                      \
    }

// ---------------------------------------------------------------------------
// K2: column pass + fused loss. grid=(16 colgroups, 8 rowtiles, 4 batches)
// = 512 blocks, block=256. Thread handles 2 ADJACENT rows (shared window).
// ---------------------------------------------------------------------------
__global__ __launch_bounds__(256) void k_colpass(float* __restrict__ out) {
    const int cg = blockIdx.x;  // 16-col group
    const int ry = blockIdx.y;
    const int b = blockIdx.z;
    const int t = threadIdx.x;
    const int base = ry * 32 - 4;

    __shared__ uint2 tile[40 * 16];  // 5 KB
    __shared__ float wsum[8];

    const int c = t & 15;
    const int rp = t >> 4;  // 0..15 -> rows 2*rp, 2*rp+1

#if __CUDA_ARCH__ >= 900
    cudaGridDependencySynchronize();  // PDL: wait for k_rowpass's writes
#endif

    const uint2* src = g_pack[b];
#pragma unroll
    for (int k = 0; k < 3; ++k) {
        int idx = t + k * 256;
        if (idx < 640) {
            int grow = base + (idx >> 4), c2 = idx & 15;
            tile[idx] = ((unsigned)grow < 256u) ? src[grow * WW + cg * 16 + c2]
                                                : make_uint2(SENTP, SENTP);
        }
    }
    __syncthreads();

    const int col = cg * 16 + c;
    const uint2* tcol = tile + c;
    const int ti0 = rp * 2 + 4;          // tile row of first pixel
    const int i0 = ry * 32 + rp * 2;     // global row of first pixel

    uint2 w[10];
#pragma unroll
    for (int j = 0; j < 10; ++j) w[j] = tcol[(ti0 - 4 + j) * 16];

    float acc = 0.0f;
    PIXEL_TERM(w, i0, col, src, acc);          // pixel A: window w[0..8]
    PIXEL_TERM((w + 1), i0 + 1, col, src, acc);  // pixel B: window w[1..9]

    // deterministic block reduction, then one REDG add of the scaled partial
#pragma unroll
    for (int o = 16; o > 0; o >>= 1) acc += __shfl_down_sync(0xFFFFFFFFu, acc, o);
    if ((t & 31) == 0) wsum[t >> 5] = acc;
    __syncthreads();
    if (t == 0) {
        float s = 0.0f;
#pragma unroll
        for (int j = 0; j < 8; ++j) s += wsum[j];
        atomicAdd(out, s * (1.0f / 262144.0f));
    }
}

extern "C" void kernel_launch(void* const* d_in, const int* in_sizes, int n_in,
                              void* d_out, int out_size) {
    const float* mo = (const float*)d_in[0];  // model_output (4,2,256,256) f32
    const float* gt = (const float*)d_in[1];  // ground_truth (4,1,256,256) f32
    float* out = (float*)d_out;

    dim3 grid1(128, BB);
    k_rowpass<<<grid1, 256>>>(mo, gt, out);

    // colpass with programmatic dependent launch (overlaps rowpass launch)
    cudaLaunchConfig_t cfg = {};
    cfg.gridDim = dim3(16, 8, BB);
    cfg.blockDim = dim3(256, 1, 1);
    cudaLaunchAttribute attr[1];
    attr[0].id = cudaLaunchAttributeProgrammaticStreamSerialization;
    attr[0].val.programmaticStreamSerializationAllowed = 1;
    cfg.attrs = attr;
    cfg.numAttrs = 1;
    cudaError_t e = cudaLaunchKernelEx(&cfg, k_colpass, out);
    if (e != cudaSuccess) {  // fallback: plain ordered launch (still correct)
        dim3 grid2(16, 8, BB);
        k_colpass<<<grid2, 256>>>(out);
    }
}